// round 8
// baseline (speedup 1.0000x reference)
#include <cuda_runtime.h>
#include <cuda_bf16.h>
#include <cstdint>

// Problem shape (fixed)
#define B_  32
#define L_  512
#define D_  768
#define H_  100
#define C_  45
#define M_  (B_ * L_)           // 16384 rows
#define NB  48                  // padded N
#define BM  64                  // rows per CTA -> 256 CTAs
#define NCHUNK 6                // 6 chunks of 128 f32 k
#define GT  256

#define ASUB 8192               // A subtile bytes (64 rows * 128B)
#define ABYT 16384              // A per-term bytes (2 subtiles)
#define BSUB 6144               // B subtile bytes (48 rows * 128B)
#define BBYT 12288              // B per-term bytes (2 subtiles)
#define BCH  (2*BBYT)           // B per chunk (hi+lo) = 24576
#define BUFSZ (2*ABYT + BCH)    // 57344 per stage
#define OFF_CVEC (2*BUFSZ)      // 114688
#define OFF_GS   (OFF_CVEC + 192)
#define SMEM_USE (OFF_GS + 256)
#define SMEM_BYTES (SMEM_USE + 1024)

#define SW(o) ((o) ^ (((o) >> 3) & 0x70))

// Device scratch. g_Wb: fused weight split hi/lo bf16, SW128 pre-swizzled.
// Layout: [chunk 0..5][hi: ka0 6KB, ka1 6KB][lo: ka0 6KB, ka1 6KB].
__device__ unsigned char g_Wb[NCHUNK * BCH];
__device__ float g_cvec[NB];

// ---------------------------------------------------------------------------
// PTX helpers (arch-portable: ldmatrix sm_75+, mma.bf16 sm_80+, cp.async sm_80+)
// ---------------------------------------------------------------------------
__device__ __forceinline__ uint32_t smem_u32(const void* p) {
    uint32_t a;
    asm("{ .reg .u64 t; cvta.to.shared.u64 t, %1; cvt.u32.u64 %0, t; }"
        : "=r"(a) : "l"(p));
    return a;
}
__device__ __forceinline__ uint32_t bf2(float lo, float hi) {
    uint32_t r;   // packed bf16x2: low half = lo, high half = hi
    asm("cvt.rn.bf16x2.f32 %0, %1, %2;" : "=r"(r) : "f"(hi), "f"(lo));
    return r;
}
__device__ __forceinline__ void ldsm4(uint32_t* r, uint32_t a) {
    asm volatile("ldmatrix.sync.aligned.m8n8.x4.shared.b16 {%0,%1,%2,%3}, [%4];"
                 : "=r"(r[0]), "=r"(r[1]), "=r"(r[2]), "=r"(r[3]) : "r"(a));
}
__device__ __forceinline__ void ldsm2(uint32_t* r, uint32_t a) {
    asm volatile("ldmatrix.sync.aligned.m8n8.x2.shared.b16 {%0,%1}, [%2];"
                 : "=r"(r[0]), "=r"(r[1]) : "r"(a));
}
__device__ __forceinline__ void mma_bf16(float* c, const uint32_t* a,
                                         uint32_t b0, uint32_t b1) {
    asm volatile(
        "mma.sync.aligned.m16n8k16.row.col.f32.bf16.bf16.f32 "
        "{%0,%1,%2,%3}, {%4,%5,%6,%7}, {%8,%9}, {%0,%1,%2,%3};"
        : "+f"(c[0]), "+f"(c[1]), "+f"(c[2]), "+f"(c[3])
        : "r"(a[0]), "r"(a[1]), "r"(a[2]), "r"(a[3]), "r"(b0), "r"(b1));
}
__device__ __forceinline__ void cpasync16(uint32_t dst, const void* src) {
    asm volatile("cp.async.cg.shared.global [%0], [%1], 16;"
                 :: "r"(dst), "l"(src) : "memory");
}
__device__ __forceinline__ void cp_commit() {
    asm volatile("cp.async.commit_group;" ::: "memory");
}
__device__ __forceinline__ void cp_wait0() {
    asm volatile("cp.async.wait_group 0;" ::: "memory");
}

// ---------------------------------------------------------------------------
// Prep (weight fuse only): 16 blocks x 256 thr; block -> 3 c, thread -> 3 d.
//   Wc[c][d] = sum_h W2[c][h] * W1[h][d]; split hi/lo bf16, SW128 pre-swizzle.
// ---------------------------------------------------------------------------
__global__ void __launch_bounds__(GT)
prep_kernel(const float* __restrict__ W1,
            const float* __restrict__ b1,
            const float* __restrict__ W2,
            const float* __restrict__ b2) {
    __shared__ float w2s[3 * H_];
    const int t = threadIdx.x;
    const int c0 = blockIdx.x * 3;

    for (int i = t; i < 3 * H_; i += GT) {
        const int c = c0 + i / H_;
        w2s[i] = (c < C_) ? W2[c * H_ + i % H_] : 0.0f;
    }
    __syncthreads();

    float acc[3][3];
#pragma unroll
    for (int ci = 0; ci < 3; ci++)
#pragma unroll
        for (int di = 0; di < 3; di++) acc[ci][di] = 0.f;

#pragma unroll 4
    for (int h = 0; h < H_; h++) {
        const float w10 = W1[h * D_ + t];
        const float w11 = W1[h * D_ + t + 256];
        const float w12 = W1[h * D_ + t + 512];
#pragma unroll
        for (int ci = 0; ci < 3; ci++) {
            const float w2v = w2s[ci * H_ + h];
            acc[ci][0] = fmaf(w2v, w10, acc[ci][0]);
            acc[ci][1] = fmaf(w2v, w11, acc[ci][1]);
            acc[ci][2] = fmaf(w2v, w12, acc[ci][2]);
        }
    }

#pragma unroll
    for (int ci = 0; ci < 3; ci++) {
        const int c = c0 + ci;
#pragma unroll
        for (int di = 0; di < 3; di++) {
            const int d = t + di * 256;
            const float s = acc[ci][di];
            __nv_bfloat16 hb = __float2bfloat16(s);
            __nv_bfloat16 lb = __float2bfloat16(s - __bfloat162float(hb));
            const int ch = d >> 7;
            const int ka = (d >> 6) & 1;
            const uint32_t off = (uint32_t)c * 128 + (uint32_t)(d & 63) * 2;
            const uint32_t sw = SW(off);
            unsigned char* base = g_Wb + ch * BCH + ka * BSUB;
            *(__nv_bfloat16*)(base + sw)        = hb;
            *(__nv_bfloat16*)(base + BBYT + sw) = lb;
        }
    }

    if (blockIdx.x == 0 && t < NB) {
        float cv = 0.0f;
        if (t < C_) {
            for (int h = 0; h < H_; h++) cv += W2[t * H_ + h] * b1[h];
            cv += b2[t];
        }
        g_cvec[t] = cv;
    }
}

// ---------------------------------------------------------------------------
// GEMM via mma.sync bf16 3-term split. CTA = 64 rows x 48 cols, 8 warps.
// Inline per-CTA compaction (ballot scan over the batch's 512 valid_ids).
// Per chunk (128 k): LDG prefetch -> convert/STS A -> cp.wait -> barrier ->
// cp.async B(next) -> 8 k16 steps x 9 MMA. One barrier per chunk.
// ---------------------------------------------------------------------------
extern "C" __global__ void __launch_bounds__(GT, 1)
gemm_kernel(const float* __restrict__ x,
            const int* __restrict__ valid_ids,
            float* __restrict__ out) {
    extern __shared__ unsigned char smem_raw[];
    __shared__ int s_wsum[9];
    const uint32_t sb_raw = smem_u32(smem_raw);
    const uint32_t pad = (1024u - (sb_raw & 1023u)) & 1023u;
    unsigned char* sm = smem_raw + pad;
    const uint32_t sb = sb_raw + pad;

    float* cS = (float*)(sm + OFF_CVEC);
    int*   gS = (int*)(sm + OFF_GS);

    const int tid  = threadIdx.x;
    const int row0 = blockIdx.x * BM;
    const int b    = row0 >> 9;          // batch (512 rows each)
    const int seg  = row0 & (L_ - 1);    // segment start within batch

    // Issue cp.async for B chunk 0 immediately (independent of compaction).
    {
        const unsigned char* bs = g_Wb;
        const uint32_t bd = sb + 2 * ABYT;   // stage 0 B region
#pragma unroll
        for (int idx = 0; idx < 6; idx++)
            cpasync16(bd + (tid + idx * GT) * 16, bs + (tid + idx * GT) * 16);
        cp_commit();
    }

    // ---- Inline compaction: ballot scan of valid_ids[b][0..511] ----
    const int p0 = 2 * tid, p1 = 2 * tid + 1;
    const int v0 = (valid_ids[b * L_ + p0] == 1);
    const int v1 = (valid_ids[b * L_ + p1] == 1);
    const int ps = v0 + v1;
    const int lane = tid & 31, w = tid >> 5;
    int incl = ps;
#pragma unroll
    for (int off = 1; off < 32; off <<= 1) {
        int y = __shfl_up_sync(0xffffffffu, incl, off);
        if (lane >= off) incl += y;
    }
    if (lane == 31) s_wsum[w] = incl;
    if (tid < BM) gS[tid] = -1;
    if (tid < NB) cS[tid] = g_cvec[tid];
    __syncthreads();
    if (tid == 0) {
        int run = 0;
#pragma unroll
        for (int i = 0; i < 8; i++) { int v = s_wsum[i]; s_wsum[i] = run; run += v; }
        s_wsum[8] = run;
    }
    __syncthreads();
    const int excl = incl - ps + s_wsum[w];
    {
        const int r0 = excl, r1 = excl + v0;
        if (v0 && r0 >= seg && r0 < seg + BM) gS[r0 - seg] = p0;
        if (v1 && r1 >= seg && r1 < seg + BM) gS[r1 - seg] = p1;
    }
    const int total = s_wsum[8];
    __syncthreads();

    // Fully-constant block: output is cvec everywhere.
    if (total <= seg) {
        float* o = out + (size_t)row0 * C_;
        for (int i = tid; i < BM * C_; i += GT)
            o[i] = cS[i % C_];
        return;
    }

    // Producer mapping: thread -> A row tid>>2, q = tid&3 -> 16-f32 groups
    const int r = tid >> 2;
    const int q = tid & 3;
    const int src = gS[r];
    const float* xr = (src >= 0)
        ? (x + ((size_t)b * L_ + src) * D_ + q * 16) : nullptr;

    // Compute mapping
    const int rw = (tid >> 5) & 3;       // row group: rows 16rw..16rw+15
    const int cw = tid >> 7;             // col group: cols 24cw..24cw+23

    // ldmatrix offsets + per-thread XOR masks (applied to FULL offset each use)
    const uint32_t aoff = (uint32_t)(rw * 16 + (lane & 15)) * 128
                        + (uint32_t)((lane >> 4) << 4);
    const uint32_t xa   = (aoff >> 3) & 0x70;
    const int l16 = lane & 15;
    uint32_t boff[3], xb[3];
#pragma unroll
    for (int j = 0; j < 3; j++) {
        boff[j] = (uint32_t)(cw * 24 + j * 8 + (l16 & 7)) * 128
                + (uint32_t)((l16 >> 3) << 4);
        xb[j]   = (boff[j] >> 3) & 0x70;
    }

    // A STS offset + mask (within a 64-col subtile)
    const uint32_t soff = (uint32_t)r * 128 + (uint32_t)q * 32;
    const uint32_t xs   = (soff >> 3) & 0x70;

    // LDG chunk 0: 8 float4 = f32 cols {ka*64 + q*16 + 0..15}, ka in {0,1}
    float4 v[8], vn[8];
#pragma unroll
    for (int ka = 0; ka < 2; ka++)
#pragma unroll
        for (int m = 0; m < 4; m++)
            v[ka * 4 + m] = xr ? *(const float4*)(xr + ka * 64 + 4 * m)
                               : make_float4(0.f, 0.f, 0.f, 0.f);

    float acc[3][4];
#pragma unroll
    for (int j = 0; j < 3; j++)
#pragma unroll
        for (int k = 0; k < 4; k++) acc[j][k] = 0.f;

    for (int ch = 0; ch < NCHUNK; ch++) {
        const int bsel = ch & 1;
        unsigned char* bufg = sm + bsel * BUFSZ;
        const uint32_t bufs = sb + bsel * BUFSZ;

        // Prefetch next chunk's A
        if (ch < NCHUNK - 1) {
            const int k0n = (ch + 1) * 128;
#pragma unroll
            for (int ka = 0; ka < 2; ka++)
#pragma unroll
                for (int m = 0; m < 4; m++)
                    vn[ka * 4 + m] = xr
                        ? *(const float4*)(xr + k0n + ka * 64 + 4 * m)
                        : make_float4(0.f, 0.f, 0.f, 0.f);
        }

        // Convert + store A hi/lo into the two 64-col subtiles
#pragma unroll
        for (int ka = 0; ka < 2; ka++) {
#pragma unroll
            for (int i = 0; i < 2; i++) {
                const float4 a = v[ka * 4 + 2 * i], c = v[ka * 4 + 2 * i + 1];
                uint4 uh, ul;
                uh.x = bf2(a.x, a.y); uh.y = bf2(a.z, a.w);
                uh.z = bf2(c.x, c.y); uh.w = bf2(c.z, c.w);
                ul.x = bf2(a.x - __uint_as_float(uh.x << 16),
                           a.y - __uint_as_float(uh.x & 0xffff0000u));
                ul.y = bf2(a.z - __uint_as_float(uh.y << 16),
                           a.w - __uint_as_float(uh.y & 0xffff0000u));
                ul.z = bf2(c.x - __uint_as_float(uh.z << 16),
                           c.y - __uint_as_float(uh.z & 0xffff0000u));
                ul.w = bf2(c.z - __uint_as_float(uh.w << 16),
                           c.w - __uint_as_float(uh.w & 0xffff0000u));
                const uint32_t sw = (soff + 16u * i) ^ xs;
                *(uint4*)(bufg + ka * ASUB + sw)        = uh;
                *(uint4*)(bufg + ABYT + ka * ASUB + sw) = ul;
            }
        }

        // B(ch) cp.async must be complete before the barrier publishes it.
        cp_wait0();
        __syncthreads();

        // Issue cp.async for B(ch+1) into the other stage (lands during MMA).
        if (ch < NCHUNK - 1) {
            const unsigned char* bs = g_Wb + (ch + 1) * BCH;
            const uint32_t bd = sb + ((ch + 1) & 1) * BUFSZ + 2 * ABYT;
#pragma unroll
            for (int idx = 0; idx < 6; idx++)
                cpasync16(bd + (tid + idx * GT) * 16, bs + (tid + idx * GT) * 16);
            cp_commit();
        }

        // Consume: 8 k16 steps x 3 n-tiles x 3 terms
        const uint32_t bB = bufs + 2 * ABYT;
#pragma unroll
        for (int s8 = 0; s8 < 8; s8++) {
            const int ka = s8 >> 2, s = s8 & 3;
            const uint32_t aA = bufs + ka * ASUB;
            const uint32_t bK = bB + ka * BSUB;
            const uint32_t ad = (aoff + 32u * s) ^ xa;
            uint32_t ah[4], al[4];
            ldsm4(ah, aA + ad);
            ldsm4(al, aA + ABYT + ad);
#pragma unroll
            for (int j = 0; j < 3; j++) {
                const uint32_t bd_ = (boff[j] + 32u * s) ^ xb[j];
                uint32_t bh[2], bl[2];
                ldsm2(bh, bK + bd_);
                ldsm2(bl, bK + BBYT + bd_);
                mma_bf16(acc[j], ah, bh[0], bh[1]);
                mma_bf16(acc[j], ah, bl[0], bl[1]);
                mma_bf16(acc[j], al, bh[0], bh[1]);
            }
        }

#pragma unroll
        for (int j = 0; j < 8; j++) v[j] = vn[j];
    }

    // Epilogue: D frag -> global. row = 16rw + lane>>2 (+8), col = 24cw+8j+2(lane&3)
    const int rbase = row0 + rw * 16 + (lane >> 2);
#pragma unroll
    for (int j = 0; j < 3; j++) {
        const int cb = cw * 24 + j * 8 + (lane & 3) * 2;
        const float c0 = cS[cb], c1 = cS[cb + 1];
#pragma unroll
        for (int h = 0; h < 2; h++) {
            float* o = out + (size_t)(rbase + 8 * h) * C_;
            if (cb < C_)     o[cb]     = acc[j][2 * h]     + c0;
            if (cb + 1 < C_) o[cb + 1] = acc[j][2 * h + 1] + c1;
        }
    }
}

// ---------------------------------------------------------------------------
extern "C" void kernel_launch(void* const* d_in, const int* in_sizes, int n_in,
                              void* d_out, int out_size) {
    const float* x   = (const float*)d_in[0];   // (32,512,768) f32
    const int*   vid = (const int*)  d_in[1];   // (32,512) i32
    const float* W1  = (const float*)d_in[2];   // (100,768)
    const float* b1  = (const float*)d_in[3];   // (100,)
    const float* W2  = (const float*)d_in[4];   // (45,100)
    const float* b2  = (const float*)d_in[5];   // (45,)
    float* out = (float*)d_out;                 // (16384,45)

    static bool attr_set = false;
    if (!attr_set) {
        cudaFuncSetAttribute(gemm_kernel,
                             cudaFuncAttributeMaxDynamicSharedMemorySize,
                             SMEM_BYTES);
        attr_set = true;
    }

    prep_kernel<<<16, GT>>>(W1, b1, W2, b2);
    gemm_kernel<<<M_ / BM, GT, SMEM_BYTES>>>(x, vid, out);
}

// round 9
// speedup vs baseline: 1.0569x; 1.0569x over previous
#include <cuda_runtime.h>
#include <cuda_bf16.h>
#include <cstdint>

// Problem shape (fixed)
#define B_  32
#define L_  512
#define D_  768
#define H_  100
#define C_  45
#define M_  (B_ * L_)           // 16384 rows
#define NB  48                  // padded N
#define BM  64                  // rows per CTA -> 256 CTAs
#define NCHUNK 6                // 6 chunks of 128 f32 k
#define GT  256

#define ASUB 8192               // A subtile bytes (64 rows * 128B)
#define ABYT 16384              // A per-term bytes (2 subtiles)
#define BSUB 6144               // B subtile bytes (48 rows * 128B)
#define BBYT 12288              // B per-term bytes (2 subtiles)
#define BCH  (2*BBYT)           // B per chunk (hi+lo) = 24576
#define BUFSZ (2*ABYT + BCH)    // 57344 per stage
#define OFF_CVEC (2*BUFSZ)      // 114688
#define OFF_GS   (OFF_CVEC + 192)
#define SMEM_USE (OFF_GS + 256)
#define SMEM_BYTES (SMEM_USE + 1024)

#define SW(o) ((o) ^ (((o) >> 3) & 0x70))

// Device scratch. g_Wb: fused weight split hi/lo bf16, SW128 pre-swizzled.
// Layout: [chunk 0..5][hi: ka0 6KB, ka1 6KB][lo: ka0 6KB, ka1 6KB].
__device__ unsigned char g_Wb[NCHUNK * BCH];
__device__ float g_cvec[NB];

// ---------------------------------------------------------------------------
// PTX helpers (arch-portable: ldmatrix sm_75+, mma.bf16 sm_80+, cp.async sm_80+)
// ---------------------------------------------------------------------------
__device__ __forceinline__ uint32_t smem_u32(const void* p) {
    uint32_t a;
    asm("{ .reg .u64 t; cvta.to.shared.u64 t, %1; cvt.u32.u64 %0, t; }"
        : "=r"(a) : "l"(p));
    return a;
}
__device__ __forceinline__ uint32_t bf2(float lo, float hi) {
    uint32_t r;   // packed bf16x2: low half = lo, high half = hi
    asm("cvt.rn.bf16x2.f32 %0, %1, %2;" : "=r"(r) : "f"(hi), "f"(lo));
    return r;
}
__device__ __forceinline__ void ldsm4(uint32_t* r, uint32_t a) {
    asm volatile("ldmatrix.sync.aligned.m8n8.x4.shared.b16 {%0,%1,%2,%3}, [%4];"
                 : "=r"(r[0]), "=r"(r[1]), "=r"(r[2]), "=r"(r[3]) : "r"(a));
}
__device__ __forceinline__ void ldsm2(uint32_t* r, uint32_t a) {
    asm volatile("ldmatrix.sync.aligned.m8n8.x2.shared.b16 {%0,%1}, [%2];"
                 : "=r"(r[0]), "=r"(r[1]) : "r"(a));
}
__device__ __forceinline__ void mma_bf16(float* c, const uint32_t* a,
                                         uint32_t b0, uint32_t b1) {
    asm volatile(
        "mma.sync.aligned.m16n8k16.row.col.f32.bf16.bf16.f32 "
        "{%0,%1,%2,%3}, {%4,%5,%6,%7}, {%8,%9}, {%0,%1,%2,%3};"
        : "+f"(c[0]), "+f"(c[1]), "+f"(c[2]), "+f"(c[3])
        : "r"(a[0]), "r"(a[1]), "r"(a[2]), "r"(a[3]), "r"(b0), "r"(b1));
}
__device__ __forceinline__ void cpasync16(uint32_t dst, const void* src) {
    asm volatile("cp.async.cg.shared.global [%0], [%1], 16;"
                 :: "r"(dst), "l"(src) : "memory");
}
__device__ __forceinline__ void cp_commit() {
    asm volatile("cp.async.commit_group;" ::: "memory");
}
__device__ __forceinline__ void cp_wait0() {
    asm volatile("cp.async.wait_group 0;" ::: "memory");
}

// ---------------------------------------------------------------------------
// Prep (weight fuse): 16 blocks x 256 thr; block bd owns d in [48bd, 48bd+48).
// W1 is read exactly ONCE chip-wide (307KB). Full W2 staged per block (288KB
// total). Thread (c3 = tid>>4, d3 = tid&15) -> 3 c x 3 d outputs, 100-h loop
// with 9 independent accumulators.
// ---------------------------------------------------------------------------
#define W2LD 102   // padded [c][h] stride: 3*102 = 306 % 32 = 18 -> distinct banks

__global__ void __launch_bounds__(GT)
prep_kernel(const float* __restrict__ W1,
            const float* __restrict__ b1,
            const float* __restrict__ W2,
            const float* __restrict__ b2) {
    __shared__ float w1s[H_ * 48];      // [h][dd]
    __shared__ float w2s[NB * W2LD];    // [c][h] padded
    const int t = threadIdx.x;
    const int d0 = blockIdx.x * 48;

    // Stage W1 slice: coalesced 192B segments per h-row
    for (int i = t; i < H_ * 48; i += GT)
        w1s[i] = W1[(i / 48) * D_ + d0 + (i % 48)];
    // Stage W2 (zero-pad c >= 45); W2 is [c][h] row-major so i = c*100+h is coalesced
    for (int i = t; i < NB * H_; i += GT) {
        const int c = i / H_, h = i - c * H_;
        w2s[c * W2LD + h] = (c < C_) ? W2[i] : 0.0f;
    }
    __syncthreads();

    const int c3 = t >> 4;   // c group: 3*c3 .. 3*c3+2
    const int d3 = t & 15;   // d group: 3*d3 .. 3*d3+2

    float acc[3][3];
#pragma unroll
    for (int ci = 0; ci < 3; ci++)
#pragma unroll
        for (int di = 0; di < 3; di++) acc[ci][di] = 0.f;

#pragma unroll 4
    for (int h = 0; h < H_; h++) {
        float w1v[3], w2v[3];
#pragma unroll
        for (int di = 0; di < 3; di++) w1v[di] = w1s[h * 48 + d3 * 3 + di];
#pragma unroll
        for (int ci = 0; ci < 3; ci++) w2v[ci] = w2s[(c3 * 3 + ci) * W2LD + h];
#pragma unroll
        for (int ci = 0; ci < 3; ci++)
#pragma unroll
            for (int di = 0; di < 3; di++)
                acc[ci][di] = fmaf(w2v[ci], w1v[di], acc[ci][di]);
    }

#pragma unroll
    for (int ci = 0; ci < 3; ci++) {
        const int c = c3 * 3 + ci;
#pragma unroll
        for (int di = 0; di < 3; di++) {
            const int d = d0 + d3 * 3 + di;
            const float s = acc[ci][di];
            __nv_bfloat16 hb = __float2bfloat16(s);
            __nv_bfloat16 lb = __float2bfloat16(s - __bfloat162float(hb));
            const int ch = d >> 7;
            const int ka = (d >> 6) & 1;
            const uint32_t off = (uint32_t)c * 128 + (uint32_t)(d & 63) * 2;
            const uint32_t sw = SW(off);
            unsigned char* base = g_Wb + ch * BCH + ka * BSUB;
            *(__nv_bfloat16*)(base + sw)        = hb;
            *(__nv_bfloat16*)(base + BBYT + sw) = lb;
        }
    }

    if (blockIdx.x == 0 && t < NB) {
        float cv = 0.0f;
        if (t < C_) {
            for (int h = 0; h < H_; h++) cv += W2[t * H_ + h] * b1[h];
            cv += b2[t];
        }
        g_cvec[t] = cv;
    }
}

// ---------------------------------------------------------------------------
// GEMM via mma.sync bf16 3-term split. CTA = 64 rows x 48 cols, 8 warps.
// Inline per-CTA compaction (ballot scan over the batch's 512 valid_ids).
// Per chunk (128 k): LDG prefetch -> convert/STS A -> cp.wait -> barrier ->
// cp.async B(next) -> 8 k16 steps x 9 MMA. One barrier per chunk.
// (Unchanged from R8: 19.0 us measured.)
// ---------------------------------------------------------------------------
extern "C" __global__ void __launch_bounds__(GT, 1)
gemm_kernel(const float* __restrict__ x,
            const int* __restrict__ valid_ids,
            float* __restrict__ out) {
    extern __shared__ unsigned char smem_raw[];
    __shared__ int s_wsum[9];
    const uint32_t sb_raw = smem_u32(smem_raw);
    const uint32_t pad = (1024u - (sb_raw & 1023u)) & 1023u;
    unsigned char* sm = smem_raw + pad;
    const uint32_t sb = sb_raw + pad;

    float* cS = (float*)(sm + OFF_CVEC);
    int*   gS = (int*)(sm + OFF_GS);

    const int tid  = threadIdx.x;
    const int row0 = blockIdx.x * BM;
    const int b    = row0 >> 9;          // batch (512 rows each)
    const int seg  = row0 & (L_ - 1);    // segment start within batch

    // Issue cp.async for B chunk 0 immediately (independent of compaction).
    {
        const unsigned char* bs = g_Wb;
        const uint32_t bd = sb + 2 * ABYT;   // stage 0 B region
#pragma unroll
        for (int idx = 0; idx < 6; idx++)
            cpasync16(bd + (tid + idx * GT) * 16, bs + (tid + idx * GT) * 16);
        cp_commit();
    }

    // ---- Inline compaction: ballot scan of valid_ids[b][0..511] ----
    const int p0 = 2 * tid, p1 = 2 * tid + 1;
    const int v0 = (valid_ids[b * L_ + p0] == 1);
    const int v1 = (valid_ids[b * L_ + p1] == 1);
    const int ps = v0 + v1;
    const int lane = tid & 31, w = tid >> 5;
    int incl = ps;
#pragma unroll
    for (int off = 1; off < 32; off <<= 1) {
        int y = __shfl_up_sync(0xffffffffu, incl, off);
        if (lane >= off) incl += y;
    }
    if (lane == 31) s_wsum[w] = incl;
    if (tid < BM) gS[tid] = -1;
    if (tid < NB) cS[tid] = g_cvec[tid];
    __syncthreads();
    if (tid == 0) {
        int run = 0;
#pragma unroll
        for (int i = 0; i < 8; i++) { int v = s_wsum[i]; s_wsum[i] = run; run += v; }
        s_wsum[8] = run;
    }
    __syncthreads();
    const int excl = incl - ps + s_wsum[w];
    {
        const int r0 = excl, r1 = excl + v0;
        if (v0 && r0 >= seg && r0 < seg + BM) gS[r0 - seg] = p0;
        if (v1 && r1 >= seg && r1 < seg + BM) gS[r1 - seg] = p1;
    }
    const int total = s_wsum[8];
    __syncthreads();

    // Fully-constant block: output is cvec everywhere.
    if (total <= seg) {
        float* o = out + (size_t)row0 * C_;
        for (int i = tid; i < BM * C_; i += GT)
            o[i] = cS[i % C_];
        return;
    }

    // Producer mapping: thread -> A row tid>>2, q = tid&3 -> 16-f32 groups
    const int r = tid >> 2;
    const int q = tid & 3;
    const int src = gS[r];
    const float* xr = (src >= 0)
        ? (x + ((size_t)b * L_ + src) * D_ + q * 16) : nullptr;

    // Compute mapping
    const int rw = (tid >> 5) & 3;       // row group: rows 16rw..16rw+15
    const int cw = tid >> 7;             // col group: cols 24cw..24cw+23

    // ldmatrix offsets + per-thread XOR masks (applied to FULL offset each use)
    const uint32_t aoff = (uint32_t)(rw * 16 + (lane & 15)) * 128
                        + (uint32_t)((lane >> 4) << 4);
    const uint32_t xa   = (aoff >> 3) & 0x70;
    const int l16 = lane & 15;
    uint32_t boff[3], xb[3];
#pragma unroll
    for (int j = 0; j < 3; j++) {
        boff[j] = (uint32_t)(cw * 24 + j * 8 + (l16 & 7)) * 128
                + (uint32_t)((l16 >> 3) << 4);
        xb[j]   = (boff[j] >> 3) & 0x70;
    }

    // A STS offset + mask (within a 64-col subtile)
    const uint32_t soff = (uint32_t)r * 128 + (uint32_t)q * 32;
    const uint32_t xs   = (soff >> 3) & 0x70;

    // LDG chunk 0: 8 float4 = f32 cols {ka*64 + q*16 + 0..15}, ka in {0,1}
    float4 v[8], vn[8];
#pragma unroll
    for (int ka = 0; ka < 2; ka++)
#pragma unroll
        for (int m = 0; m < 4; m++)
            v[ka * 4 + m] = xr ? *(const float4*)(xr + ka * 64 + 4 * m)
                               : make_float4(0.f, 0.f, 0.f, 0.f);

    float acc[3][4];
#pragma unroll
    for (int j = 0; j < 3; j++)
#pragma unroll
        for (int k = 0; k < 4; k++) acc[j][k] = 0.f;

    for (int ch = 0; ch < NCHUNK; ch++) {
        const int bsel = ch & 1;
        unsigned char* bufg = sm + bsel * BUFSZ;
        const uint32_t bufs = sb + bsel * BUFSZ;

        // Prefetch next chunk's A
        if (ch < NCHUNK - 1) {
            const int k0n = (ch + 1) * 128;
#pragma unroll
            for (int ka = 0; ka < 2; ka++)
#pragma unroll
                for (int m = 0; m < 4; m++)
                    vn[ka * 4 + m] = xr
                        ? *(const float4*)(xr + k0n + ka * 64 + 4 * m)
                        : make_float4(0.f, 0.f, 0.f, 0.f);
        }

        // Convert + store A hi/lo into the two 64-col subtiles
#pragma unroll
        for (int ka = 0; ka < 2; ka++) {
#pragma unroll
            for (int i = 0; i < 2; i++) {
                const float4 a = v[ka * 4 + 2 * i], c = v[ka * 4 + 2 * i + 1];
                uint4 uh, ul;
                uh.x = bf2(a.x, a.y); uh.y = bf2(a.z, a.w);
                uh.z = bf2(c.x, c.y); uh.w = bf2(c.z, c.w);
                ul.x = bf2(a.x - __uint_as_float(uh.x << 16),
                           a.y - __uint_as_float(uh.x & 0xffff0000u));
                ul.y = bf2(a.z - __uint_as_float(uh.y << 16),
                           a.w - __uint_as_float(uh.y & 0xffff0000u));
                ul.z = bf2(c.x - __uint_as_float(uh.z << 16),
                           c.y - __uint_as_float(uh.z & 0xffff0000u));
                ul.w = bf2(c.z - __uint_as_float(uh.w << 16),
                           c.w - __uint_as_float(uh.w & 0xffff0000u));
                const uint32_t sw = (soff + 16u * i) ^ xs;
                *(uint4*)(bufg + ka * ASUB + sw)        = uh;
                *(uint4*)(bufg + ABYT + ka * ASUB + sw) = ul;
            }
        }

        // B(ch) cp.async must be complete before the barrier publishes it.
        cp_wait0();
        __syncthreads();

        // Issue cp.async for B(ch+1) into the other stage (lands during MMA).
        if (ch < NCHUNK - 1) {
            const unsigned char* bs = g_Wb + (ch + 1) * BCH;
            const uint32_t bd = sb + ((ch + 1) & 1) * BUFSZ + 2 * ABYT;
#pragma unroll
            for (int idx = 0; idx < 6; idx++)
                cpasync16(bd + (tid + idx * GT) * 16, bs + (tid + idx * GT) * 16);
            cp_commit();
        }

        // Consume: 8 k16 steps x 3 n-tiles x 3 terms
        const uint32_t bB = bufs + 2 * ABYT;
#pragma unroll
        for (int s8 = 0; s8 < 8; s8++) {
            const int ka = s8 >> 2, s = s8 & 3;
            const uint32_t aA = bufs + ka * ASUB;
            const uint32_t bK = bB + ka * BSUB;
            const uint32_t ad = (aoff + 32u * s) ^ xa;
            uint32_t ah[4], al[4];
            ldsm4(ah, aA + ad);
            ldsm4(al, aA + ABYT + ad);
#pragma unroll
            for (int j = 0; j < 3; j++) {
                const uint32_t bd_ = (boff[j] + 32u * s) ^ xb[j];
                uint32_t bh[2], bl[2];
                ldsm2(bh, bK + bd_);
                ldsm2(bl, bK + BBYT + bd_);
                mma_bf16(acc[j], ah, bh[0], bh[1]);
                mma_bf16(acc[j], ah, bl[0], bl[1]);
                mma_bf16(acc[j], al, bh[0], bh[1]);
            }
        }

#pragma unroll
        for (int j = 0; j < 8; j++) v[j] = vn[j];
    }

    // Epilogue: D frag -> global. row = 16rw + lane>>2 (+8), col = 24cw+8j+2(lane&3)
    const int rbase = row0 + rw * 16 + (lane >> 2);
#pragma unroll
    for (int j = 0; j < 3; j++) {
        const int cb = cw * 24 + j * 8 + (lane & 3) * 2;
        const float c0 = cS[cb], c1 = cS[cb + 1];
#pragma unroll
        for (int h = 0; h < 2; h++) {
            float* o = out + (size_t)(rbase + 8 * h) * C_;
            if (cb < C_)     o[cb]     = acc[j][2 * h]     + c0;
            if (cb + 1 < C_) o[cb + 1] = acc[j][2 * h + 1] + c1;
        }
    }
}

// ---------------------------------------------------------------------------
extern "C" void kernel_launch(void* const* d_in, const int* in_sizes, int n_in,
                              void* d_out, int out_size) {
    const float* x   = (const float*)d_in[0];   // (32,512,768) f32
    const int*   vid = (const int*)  d_in[1];   // (32,512) i32
    const float* W1  = (const float*)d_in[2];   // (100,768)
    const float* b1  = (const float*)d_in[3];   // (100,)
    const float* W2  = (const float*)d_in[4];   // (45,100)
    const float* b2  = (const float*)d_in[5];   // (45,)
    float* out = (float*)d_out;                 // (16384,45)

    static bool attr_set = false;
    if (!attr_set) {
        cudaFuncSetAttribute(gemm_kernel,
                             cudaFuncAttributeMaxDynamicSharedMemorySize,
                             SMEM_BYTES);
        attr_set = true;
    }

    prep_kernel<<<16, GT>>>(W1, b1, W2, b2);
    gemm_kernel<<<M_ / BM, GT, SMEM_BYTES>>>(x, vid, out);
}

// round 10
// speedup vs baseline: 1.3131x; 1.2424x over previous
#include <cuda_runtime.h>
#include <cstdint>

// Problem shape (fixed)
#define B_  32
#define L_  512
#define D_  768
#define H_  100
#define C_  45
#define M_  (B_ * L_)           // 16384 rows
#define NB  48                  // padded N
#define BM  64                  // rows per CTA -> 256 CTAs
#define NCHUNK 6                // 6 chunks of 128 f32 k
#define GT  256
#define NSTG 3                  // cp.async pipeline stages

#define ASUB 8192               // A subtile (64 rows * 128B = 32 f32 k)
#define ATOT 32768              // A per stage (4 subtiles, k=128)
#define BSUB 6144               // B subtile (48 rows * 128B)
#define BTOT 24576              // B per stage (4 subtiles)
#define BCH  BTOT               // B bytes per chunk in global
#define BUFSZ (ATOT + BTOT)     // 57344 per stage
#define OFF_CVEC (NSTG*BUFSZ)   // 172032
#define OFF_GS   (OFF_CVEC + 192)
#define SMEM_USE (OFF_GS + 256)
#define SMEM_BYTES (SMEM_USE + 1024)

#define SW(o) ((o) ^ (((o) >> 3) & 0x70))

// Device scratch. g_Wb: fused weight, tf32(f32) SW128 pre-swizzled.
// Layout: [chunk 0..5][ka 0..3][48 rows x 128B].
__device__ unsigned char g_Wb[NCHUNK * BCH];
__device__ float g_cvec[NB];

// ---------------------------------------------------------------------------
// PTX helpers (arch-portable: ldmatrix sm_75+, mma.tf32 sm_80+, cp.async sm_80+)
// ---------------------------------------------------------------------------
__device__ __forceinline__ uint32_t smem_u32(const void* p) {
    uint32_t a;
    asm("{ .reg .u64 t; cvta.to.shared.u64 t, %1; cvt.u32.u64 %0, t; }"
        : "=r"(a) : "l"(p));
    return a;
}
__device__ __forceinline__ void ldsm4(uint32_t* r, uint32_t a) {
    asm volatile("ldmatrix.sync.aligned.m8n8.x4.shared.b16 {%0,%1,%2,%3}, [%4];"
                 : "=r"(r[0]), "=r"(r[1]), "=r"(r[2]), "=r"(r[3]) : "r"(a));
}
__device__ __forceinline__ void ldsm2(uint32_t* r, uint32_t a) {
    asm volatile("ldmatrix.sync.aligned.m8n8.x2.shared.b16 {%0,%1}, [%2];"
                 : "=r"(r[0]), "=r"(r[1]) : "r"(a));
}
__device__ __forceinline__ void mma_tf32(float* c, const uint32_t* a,
                                         uint32_t b0, uint32_t b1) {
    asm volatile(
        "mma.sync.aligned.m16n8k8.row.col.f32.tf32.tf32.f32 "
        "{%0,%1,%2,%3}, {%4,%5,%6,%7}, {%8,%9}, {%0,%1,%2,%3};"
        : "+f"(c[0]), "+f"(c[1]), "+f"(c[2]), "+f"(c[3])
        : "r"(a[0]), "r"(a[1]), "r"(a[2]), "r"(a[3]), "r"(b0), "r"(b1));
}
__device__ __forceinline__ void cpasync16(uint32_t dst, const void* src) {
    asm volatile("cp.async.cg.shared.global [%0], [%1], 16;"
                 :: "r"(dst), "l"(src) : "memory");
}
// zero-fills when srcsz == 0
__device__ __forceinline__ void cpasync16z(uint32_t dst, const void* src,
                                           uint32_t srcsz) {
    asm volatile("cp.async.cg.shared.global [%0], [%1], 16, %2;"
                 :: "r"(dst), "l"(src), "r"(srcsz) : "memory");
}
__device__ __forceinline__ void cp_commit() {
    asm volatile("cp.async.commit_group;" ::: "memory");
}
__device__ __forceinline__ void cp_wait1() {
    asm volatile("cp.async.wait_group 1;" ::: "memory");
}
__device__ __forceinline__ void cp_wait0() {
    asm volatile("cp.async.wait_group 0;" ::: "memory");
}
__device__ __forceinline__ uint32_t tf32rn(float s) {
    uint32_t u;
    asm("cvt.rn.tf32.f32 %0, %1;" : "=r"(u) : "f"(s));
    return u;
}

// ---------------------------------------------------------------------------
// Prep (weight fuse): 48 blocks x 256 thr; block bd owns d in [16bd, 16bd+16).
//   Wc[c][d] = sum_h W2[c][h] * W1[h][d], rounded rn to tf32, SW128 swizzled.
// ---------------------------------------------------------------------------
#define W2LD 102

__global__ void __launch_bounds__(GT)
prep_kernel(const float* __restrict__ W1,
            const float* __restrict__ b1,
            const float* __restrict__ W2,
            const float* __restrict__ b2) {
    __shared__ float w1s[H_ * 16];      // [h][dd]
    __shared__ float w2s[NB * W2LD];    // [c][h] padded
    const int t = threadIdx.x;
    const int d0 = blockIdx.x * 16;

    for (int i = t; i < H_ * 16; i += GT)
        w1s[i] = W1[(i >> 4) * D_ + d0 + (i & 15)];
    for (int i = t; i < NB * H_; i += GT) {
        const int c = i / H_, h = i - c * H_;
        w2s[c * W2LD + h] = (c < C_) ? W2[i] : 0.0f;
    }
    __syncthreads();

    const int c3 = t >> 4;   // c group: 3*c3 .. 3*c3+2
    const int dd = t & 15;   // one d
    const int d  = d0 + dd;

    float acc[3] = {0.f, 0.f, 0.f};
#pragma unroll 4
    for (int h = 0; h < H_; h++) {
        const float w1v = w1s[h * 16 + dd];
#pragma unroll
        for (int ci = 0; ci < 3; ci++)
            acc[ci] = fmaf(w2s[(c3 * 3 + ci) * W2LD + h], w1v, acc[ci]);
    }

    const int ch = d >> 7;
    const int ka = (d >> 5) & 3;
    unsigned char* base = g_Wb + ch * BCH + ka * BSUB;
#pragma unroll
    for (int ci = 0; ci < 3; ci++) {
        const int c = c3 * 3 + ci;
        const uint32_t off = (uint32_t)c * 128 + (uint32_t)(d & 31) * 4;
        *(uint32_t*)(base + SW(off)) = tf32rn(acc[ci]);
    }

    if (blockIdx.x == 0 && t < NB) {
        float cv = 0.0f;
        if (t < C_) {
            for (int h = 0; h < H_; h++) cv += W2[t * H_ + h] * b1[h];
            cv += b2[t];
        }
        g_cvec[t] = cv;
    }
}

// ---------------------------------------------------------------------------
// GEMM via mma.sync tf32 single-pass. CTA = 64 rows x 48 cols, 8 warps.
// Producer is PURE cp.async (A: f32 direct from gathered rows; B: linear copy
// of pre-swizzled tf32 weights). 3-stage pipeline, one barrier per chunk.
// ---------------------------------------------------------------------------
extern "C" __global__ void __launch_bounds__(GT, 1)
gemm_kernel(const float* __restrict__ x,
            const int* __restrict__ valid_ids,
            float* __restrict__ out) {
    extern __shared__ unsigned char smem_raw[];
    __shared__ int s_wsum[9];
    const uint32_t sb_raw = smem_u32(smem_raw);
    const uint32_t pad = (1024u - (sb_raw & 1023u)) & 1023u;
    unsigned char* sm = smem_raw + pad;
    const uint32_t sb = sb_raw + pad;

    float* cS = (float*)(sm + OFF_CVEC);
    int*   gS = (int*)(sm + OFF_GS);

    const int tid  = threadIdx.x;
    const int row0 = blockIdx.x * BM;
    const int b    = row0 >> 9;          // batch
    const int seg  = row0 & (L_ - 1);    // segment start within batch

    // ---- Inline compaction: ballot scan of valid_ids[b][0..511] ----
    const int p0 = 2 * tid, p1 = 2 * tid + 1;
    const int v0 = (valid_ids[b * L_ + p0] == 1);
    const int v1 = (valid_ids[b * L_ + p1] == 1);
    const int ps = v0 + v1;
    const int lane = tid & 31, w = tid >> 5;
    int incl = ps;
#pragma unroll
    for (int off = 1; off < 32; off <<= 1) {
        int y = __shfl_up_sync(0xffffffffu, incl, off);
        if (lane >= off) incl += y;
    }
    if (lane == 31) s_wsum[w] = incl;
    if (tid < BM) gS[tid] = -1;
    if (tid < NB) cS[tid] = g_cvec[tid];
    __syncthreads();
    if (tid == 0) {
        int run = 0;
#pragma unroll
        for (int i = 0; i < 8; i++) { int v = s_wsum[i]; s_wsum[i] = run; run += v; }
        s_wsum[8] = run;
    }
    __syncthreads();
    const int excl = incl - ps + s_wsum[w];
    {
        const int r0 = excl, r1 = excl + v0;
        if (v0 && r0 >= seg && r0 < seg + BM) gS[r0 - seg] = p0;
        if (v1 && r1 >= seg && r1 < seg + BM) gS[r1 - seg] = p1;
    }
    const int total = s_wsum[8];
    __syncthreads();

    // Fully-constant block: output is cvec everywhere.
    if (total <= seg) {
        float* o = out + (size_t)row0 * C_;
        for (int i = tid; i < BM * C_; i += GT)
            o[i] = cS[i % C_];
        return;
    }

    // Producer mapping: thread -> A row r = tid>>2, slots q*2, q*2+1 per subtile
    const int r = tid >> 2;
    const int q = tid & 3;
    const int src = gS[r];
    const uint32_t srcsz = (src >= 0) ? 16u : 0u;
    const float* xrow = x + ((size_t)b * L_ + (src >= 0 ? src : 0)) * D_;
    const uint32_t xs = (((uint32_t)r * 128) >> 3) & 0x70;  // row swizzle bits

    // Consumer mapping
    const int rw = (tid >> 5) & 3;       // rows 16rw..16rw+15
    const int cw = tid >> 7;             // cols 24cw..24cw+23
    const uint32_t aoff = (uint32_t)(rw * 16 + (lane & 15)) * 128
                        + (uint32_t)((lane >> 4) << 4);
    const uint32_t xa   = (aoff >> 3) & 0x70;
    const int l16 = lane & 15;
    uint32_t boff[3], xb[3];
#pragma unroll
    for (int j = 0; j < 3; j++) {
        boff[j] = (uint32_t)(cw * 24 + j * 8 + (l16 & 7)) * 128
                + (uint32_t)((l16 >> 3) << 4);
        xb[j]   = (boff[j] >> 3) & 0x70;
    }

    // Group issue: B (pre-swizzled, linear) then A (gathered, swizzled dst)
    auto issue_group = [&](int g) {
        const uint32_t bufs = sb + (g % NSTG) * BUFSZ;
        const unsigned char* bs = g_Wb + g * BCH;
        const uint32_t bd = bufs + ATOT;
#pragma unroll
        for (int idx = 0; idx < 6; idx++)
            cpasync16(bd + (tid + idx * GT) * 16, bs + (tid + idx * GT) * 16);
        const float* xc = xrow + g * 128;
#pragma unroll
        for (int ka = 0; ka < 4; ka++) {
#pragma unroll
            for (int i = 0; i < 2; i++) {
                const uint32_t s = (uint32_t)q * 2 + i;
                const uint32_t dst = bufs + ka * ASUB
                                   + (((uint32_t)r * 128 + s * 16) ^ xs);
                cpasync16z(dst, xc + ka * 32 + s * 4, srcsz);
            }
        }
        cp_commit();
    };

    // Prologue: stages 0,1 in flight
    issue_group(0);
    issue_group(1);

    float acc[3][4];
#pragma unroll
    for (int j = 0; j < 3; j++)
#pragma unroll
        for (int k = 0; k < 4; k++) acc[j][k] = 0.f;

    for (int ch = 0; ch < NCHUNK; ch++) {
        if (ch < NCHUNK - 1) cp_wait1(); else cp_wait0();
        __syncthreads();
        if (ch + 2 < NCHUNK) issue_group(ch + 2);

        const uint32_t bufs = sb + (ch % NSTG) * BUFSZ;
        const uint32_t bB = bufs + ATOT;
#pragma unroll
        for (int s8 = 0; s8 < 16; s8++) {
            const int ka = s8 >> 2, s = s8 & 3;
            const uint32_t aA = bufs + ka * ASUB;
            const uint32_t bK = bB + ka * BSUB;
            uint32_t ah[4];
            ldsm4(ah, aA + ((aoff + 32u * s) ^ xa));
#pragma unroll
            for (int j = 0; j < 3; j++) {
                uint32_t bv[2];
                ldsm2(bv, bK + ((boff[j] + 32u * s) ^ xb[j]));
                mma_tf32(acc[j], ah, bv[0], bv[1]);
            }
        }
    }

    // Epilogue: row = 16rw + lane>>2 (+8), col = 24cw + 8j + 2(lane&3)
    const int rbase = row0 + rw * 16 + (lane >> 2);
#pragma unroll
    for (int j = 0; j < 3; j++) {
        const int cb = cw * 24 + j * 8 + (lane & 3) * 2;
        const float c0 = cS[cb], c1 = cS[cb + 1];
#pragma unroll
        for (int h = 0; h < 2; h++) {
            float* o = out + (size_t)(rbase + 8 * h) * C_;
            if (cb < C_)     o[cb]     = acc[j][2 * h]     + c0;
            if (cb + 1 < C_) o[cb + 1] = acc[j][2 * h + 1] + c1;
        }
    }
}

// ---------------------------------------------------------------------------
extern "C" void kernel_launch(void* const* d_in, const int* in_sizes, int n_in,
                              void* d_out, int out_size) {
    const float* x   = (const float*)d_in[0];   // (32,512,768) f32
    const int*   vid = (const int*)  d_in[1];   // (32,512) i32
    const float* W1  = (const float*)d_in[2];   // (100,768)
    const float* b1  = (const float*)d_in[3];   // (100,)
    const float* W2  = (const float*)d_in[4];   // (45,100)
    const float* b2  = (const float*)d_in[5];   // (45,)
    float* out = (float*)d_out;                 // (16384,45)

    static bool attr_set = false;
    if (!attr_set) {
        cudaFuncSetAttribute(gemm_kernel,
                             cudaFuncAttributeMaxDynamicSharedMemorySize,
                             SMEM_BYTES);
        attr_set = true;
    }

    prep_kernel<<<48, GT>>>(W1, b1, W2, b2);
    gemm_kernel<<<M_ / BM, GT, SMEM_BYTES>>>(x, vid, out);
}